// round 16
// baseline (speedup 1.0000x reference)
#include <cuda_runtime.h>
#include <cuda_fp16.h>

// ---------------------------------------------------------------------------
// GCNRegression: 2x GCNConv(+relu) + linear head.
// N=100000, E=1.6M, F=128, H=64. edge_index arrives int32.
//
// R16 = R15 (best, 149.5us) + ONE change: agg_body rewritten with 8-edge
// unroll and TWO independent accumulator pairs. The agg kernels were
// latency-bound (measured ~32us vs ~18us LTS floor): MLP was 4 against
// ~250cyc L2 gather latency and all FMAs fed one serial (ax,ay) chain.
// Now 8 gathers in flight, FMA chain depth halved.
// ---------------------------------------------------------------------------

#define NMAX 100000
#define EMAX 1600000
#define HID 64
#define SCAN_CHUNK 4096

__device__ __align__(16) float2 g_dc[NMAX];            // {deg_sum, count}
__device__ __align__(16) float  g_dis[NMAX];
__device__ __align__(16) int    g_rowptr[NMAX + 1];
__device__ __align__(16) int    g_pos[NMAX];
__device__ __align__(16) int    g_bsum[1024];
__device__ __align__(16) int    g_boff[1024];
__device__ __align__(16) float2 g_edge[EMAX];          // {src_as_float_bits, coef}
__device__ __align__(16) __half g_bufA[(size_t)NMAX * HID];
__device__ __align__(16) __half g_bufB[(size_t)NMAX * HID];

// ---- zero {deg, cnt} -------------------------------------------------------
__global__ void k_zero_dc(int n) {
    int i = blockIdx.x * blockDim.x + threadIdx.x;
    if (i < n) g_dc[i] = make_float2(0.f, 0.f);
}

// ---- weighted in-degree + histogram, one vector RED per edge ---------------
__global__ void k_deg_hist(const int* __restrict__ dst,
                           const float* __restrict__ ew, int E) {
    int e = blockIdx.x * blockDim.x + threadIdx.x;
    if (e < E) {
        int d = dst[e];
        float w = ew[e];
        asm volatile("red.global.add.v2.f32 [%0], {%1,%2};"
                     :: "l"(&g_dc[d]), "f"(w), "f"(1.0f) : "memory");
    }
}

// ---- scan phase 1 over counts (+ fused dis = rsqrt(1+deg)) -----------------
__global__ void k_scan1(int n) {
    __shared__ int ts[1024];
    int t = threadIdx.x, b = blockIdx.x;
    int base = b * SCAN_CHUNK + t * 4;
    int c[4];
#pragma unroll
    for (int r = 0; r < 4; r++) {
        if (base + r < n) {
            float2 dc = g_dc[base + r];
            c[r] = (int)dc.y;
            g_dis[base + r] = rsqrtf(1.0f + dc.x);
        } else c[r] = 0;
    }
    int s = c[0] + c[1] + c[2] + c[3];
    ts[t] = s;
    __syncthreads();
    for (int d = 1; d < 1024; d <<= 1) {
        int v = (t >= d) ? ts[t - d] : 0;
        __syncthreads();
        ts[t] += v;
        __syncthreads();
    }
    int excl = ts[t] - s;
    if (base + 0 < n) g_rowptr[base + 0] = excl;
    if (base + 1 < n) g_rowptr[base + 1] = excl + c[0];
    if (base + 2 < n) g_rowptr[base + 2] = excl + c[0] + c[1];
    if (base + 3 < n) g_rowptr[base + 3] = excl + c[0] + c[1] + c[2];
    if (t == 1023) g_bsum[b] = ts[1023];
}

// ---- scan phase 2: scan block sums (nb <= 1024) ----------------------------
__global__ void k_scan2(int nb, int n, int E) {
    __shared__ int ts[1024];
    int t = threadIdx.x;
    int v = (t < nb) ? g_bsum[t] : 0;
    ts[t] = v;
    __syncthreads();
    for (int d = 1; d < 1024; d <<= 1) {
        int u = (t >= d) ? ts[t - d] : 0;
        __syncthreads();
        ts[t] += u;
        __syncthreads();
    }
    if (t < nb) g_boff[t] = ts[t] - v;
    if (t == 0) g_rowptr[n] = E;
}

// ---- scan phase 3: add block offsets, init cursors -------------------------
__global__ void k_scan3(int n) {
    int i = blockIdx.x * blockDim.x + threadIdx.x;
    if (i < n) {
        int r = g_rowptr[i] + g_boff[i / SCAN_CHUNK];
        g_rowptr[i] = r;
        g_pos[i] = r;
    }
}

// ---- scatter edges into dst-sorted CSR order (packed meta) -----------------
__global__ void k_scatter(const int* __restrict__ src,
                          const int* __restrict__ dst,
                          const float* __restrict__ ew, int E) {
    int e = blockIdx.x * blockDim.x + threadIdx.x;
    if (e >= E) return;
    int s = src[e];
    int d = dst[e];
    int p = atomicAdd(&g_pos[d], 1);
    g_edge[p] = make_float2(__int_as_float(s), g_dis[s] * ew[e] * g_dis[d]);
}

// ---- tensor-core GEMM: Y[n,64] = X[n,K] @ W[64,K]^T  (fp16 in, f32 acc) ----
// 256 thr = 8 warps; block tile 128 rows x 64 cols; warp = 16 rows x 64 cols
// (8 n-tiles of m16n8k16). K chunked by 64 halves. Smem rows padded to 72
// halves (144B pitch) -> fragment LDS.32s (8 rows apart) are conflict-free.
#define XPITCH 72

template <int K, bool F16IN>
__global__ __launch_bounds__(256) void k_gemm_tc(
        const void* __restrict__ Xv, const float* __restrict__ W,
        __half* __restrict__ Y, int n) {
    __shared__ __half Xs[128][XPITCH];
    __shared__ __half Wt[64][XPITCH];

    const int tid  = threadIdx.x;
    const int warp = tid >> 5;
    const int lane = tid & 31;
    const int g    = lane >> 2;
    const int tq   = lane & 3;
    const int row0 = blockIdx.x * 128;
    const int rA   = warp * 16 + g;

    float d0[8], d1[8], d2[8], d3[8];
#pragma unroll
    for (int t = 0; t < 8; t++) { d0[t] = d1[t] = d2[t] = d3[t] = 0.f; }

    for (int kc = 0; kc < K; kc += 64) {
        if (kc) __syncthreads();
        if (F16IN) {
            const uint4* X8 = (const uint4*)Xv;
#pragma unroll
            for (int i = 0; i < 4; i++) {
                int idx = tid + i * 256;
                int r = idx >> 3, q = idx & 7;
                int row = row0 + r;
                uint4 u = (row < n) ? X8[(size_t)row * (K / 8) + (kc >> 3) + q]
                                    : make_uint4(0u, 0u, 0u, 0u);
                *(uint4*)&Xs[r][q * 8] = u;
            }
        } else {
            const float4* X4 = (const float4*)Xv;
#pragma unroll
            for (int i = 0; i < 8; i++) {
                int idx = tid + i * 256;
                int r = idx >> 4, q = idx & 15;
                int row = row0 + r;
                float4 a = (row < n) ? X4[(size_t)row * (K / 4) + (kc >> 2) + q]
                                     : make_float4(0.f, 0.f, 0.f, 0.f);
                __half2 p0 = __floats2half2_rn(a.x, a.y);
                __half2 p1 = __floats2half2_rn(a.z, a.w);
                *(uint2*)&Xs[r][q * 4] = make_uint2(*(unsigned*)&p0, *(unsigned*)&p1);
            }
        }
#pragma unroll
        for (int i = 0; i < 16; i++) {
            int idx = tid + i * 256;
            int c = idx >> 6, k = idx & 63;
            Wt[c][k] = __float2half(W[(size_t)c * K + kc + k]);
        }
        __syncthreads();

#pragma unroll
        for (int ks = 0; ks < 64; ks += 16) {
            unsigned a0 = *(const unsigned*)&Xs[rA][ks + tq * 2];
            unsigned a1 = *(const unsigned*)&Xs[rA + 8][ks + tq * 2];
            unsigned a2 = *(const unsigned*)&Xs[rA][ks + tq * 2 + 8];
            unsigned a3 = *(const unsigned*)&Xs[rA + 8][ks + tq * 2 + 8];
#pragma unroll
            for (int nt = 0; nt < 8; nt++) {
                unsigned b0 = *(const unsigned*)&Wt[nt * 8 + g][ks + tq * 2];
                unsigned b1 = *(const unsigned*)&Wt[nt * 8 + g][ks + tq * 2 + 8];
                asm volatile(
                    "mma.sync.aligned.m16n8k16.row.col.f32.f16.f16.f32 "
                    "{%0,%1,%2,%3}, {%4,%5,%6,%7}, {%8,%9}, {%0,%1,%2,%3};"
                    : "+f"(d0[nt]), "+f"(d1[nt]), "+f"(d2[nt]), "+f"(d3[nt])
                    : "r"(a0), "r"(a1), "r"(a2), "r"(a3), "r"(b0), "r"(b1));
            }
        }
    }

    int rowA = row0 + warp * 16 + g;
    int rowB = rowA + 8;
#pragma unroll
    for (int nt = 0; nt < 8; nt++) {
        int col = nt * 8 + tq * 2;
        if (rowA < n) {
            __half2 p = __floats2half2_rn(d0[nt], d1[nt]);
            *(unsigned*)&Y[(size_t)rowA * HID + col] = *(unsigned*)&p;
        }
        if (rowB < n) {
            __half2 p = __floats2half2_rn(d2[nt], d3[nt]);
            *(unsigned*)&Y[(size_t)rowB * HID + col] = *(unsigned*)&p;
        }
    }
}

// ---- segmented-sum body over fp16 rows: acc (float2/lane) ------------------
// R16: 8-edge unroll, 2 independent accumulator pairs (MLP 8, chain depth /2)
__device__ __forceinline__ float2 ld_h2(const __half* __restrict__ xw,
                                        int s, int lane) {
    unsigned bits = __ldg((const unsigned*)(xw + (size_t)s * HID) + lane);
    return __half22float2(*(__half2*)&bits);
}

__device__ __forceinline__ void agg_body(const __half* __restrict__ xw,
                                         int node, int lane,
                                         float& ax, float& ay) {
    int j   = g_rowptr[node];
    int end = g_rowptr[node + 1];
    float ax0 = 0.f, ay0 = 0.f, ax1 = 0.f, ay1 = 0.f;
    for (; j + 7 < end; j += 8) {
        float2 m0 = g_edge[j],     m1 = g_edge[j + 1];
        float2 m2 = g_edge[j + 2], m3 = g_edge[j + 3];
        float2 m4 = g_edge[j + 4], m5 = g_edge[j + 5];
        float2 m6 = g_edge[j + 6], m7 = g_edge[j + 7];
        float2 v0 = ld_h2(xw, __float_as_int(m0.x), lane);
        float2 v1 = ld_h2(xw, __float_as_int(m1.x), lane);
        float2 v2 = ld_h2(xw, __float_as_int(m2.x), lane);
        float2 v3 = ld_h2(xw, __float_as_int(m3.x), lane);
        float2 v4 = ld_h2(xw, __float_as_int(m4.x), lane);
        float2 v5 = ld_h2(xw, __float_as_int(m5.x), lane);
        float2 v6 = ld_h2(xw, __float_as_int(m6.x), lane);
        float2 v7 = ld_h2(xw, __float_as_int(m7.x), lane);
        ax0 = fmaf(m0.y, v0.x, ax0); ay0 = fmaf(m0.y, v0.y, ay0);
        ax1 = fmaf(m1.y, v1.x, ax1); ay1 = fmaf(m1.y, v1.y, ay1);
        ax0 = fmaf(m2.y, v2.x, ax0); ay0 = fmaf(m2.y, v2.y, ay0);
        ax1 = fmaf(m3.y, v3.x, ax1); ay1 = fmaf(m3.y, v3.y, ay1);
        ax0 = fmaf(m4.y, v4.x, ax0); ay0 = fmaf(m4.y, v4.y, ay0);
        ax1 = fmaf(m5.y, v5.x, ax1); ay1 = fmaf(m5.y, v5.y, ay1);
        ax0 = fmaf(m6.y, v6.x, ax0); ay0 = fmaf(m6.y, v6.y, ay0);
        ax1 = fmaf(m7.y, v7.x, ax1); ay1 = fmaf(m7.y, v7.y, ay1);
    }
    if (j + 3 < end) {
        float2 m0 = g_edge[j],     m1 = g_edge[j + 1];
        float2 m2 = g_edge[j + 2], m3 = g_edge[j + 3];
        float2 v0 = ld_h2(xw, __float_as_int(m0.x), lane);
        float2 v1 = ld_h2(xw, __float_as_int(m1.x), lane);
        float2 v2 = ld_h2(xw, __float_as_int(m2.x), lane);
        float2 v3 = ld_h2(xw, __float_as_int(m3.x), lane);
        ax0 = fmaf(m0.y, v0.x, ax0); ay0 = fmaf(m0.y, v0.y, ay0);
        ax1 = fmaf(m1.y, v1.x, ax1); ay1 = fmaf(m1.y, v1.y, ay1);
        ax0 = fmaf(m2.y, v2.x, ax0); ay0 = fmaf(m2.y, v2.y, ay0);
        ax1 = fmaf(m3.y, v3.x, ax1); ay1 = fmaf(m3.y, v3.y, ay1);
        j += 4;
    }
    for (; j < end; j++) {
        float2 m = g_edge[j];
        float2 v = ld_h2(xw, __float_as_int(m.x), lane);
        ax0 = fmaf(m.y, v.x, ax0); ay0 = fmaf(m.y, v.y, ay0);
    }
    ax = ax0 + ax1;
    ay = ay0 + ay1;
}

// ---- layer aggregation + self-loop + bias + relu (1 warp/node) -------------
__global__ void k_agg_relu(const __half* __restrict__ xw,
                           const float* __restrict__ b,
                           __half* __restrict__ out, int n) {
    int node = (blockIdx.x * blockDim.x + threadIdx.x) >> 5;
    int lane = threadIdx.x & 31;
    if (node >= n) return;
    float ax = 0.f, ay = 0.f;
    agg_body(xw, node, lane, ax, ay);
    float ds = g_dis[node];
    float d2 = ds * ds;
    float2 xv = ld_h2(xw, node, lane);
    float2 bb = __ldg((const float2*)b + lane);
    float rx = fmaxf(fmaf(d2, xv.x, ax) + bb.x, 0.f);
    float ry = fmaxf(fmaf(d2, xv.y, ay) + bb.y, 0.f);
    __half2 p = __floats2half2_rn(rx, ry);
    ((unsigned*)(out + (size_t)node * HID))[lane] = *(unsigned*)&p;
}

// ---- final aggregation + relu + head dot W3 (1 warp/node) ------------------
__global__ void k_agg_head(const __half* __restrict__ xw,
                           const float* __restrict__ b2,
                           const float* __restrict__ W3,
                           const float* __restrict__ b3,
                           float* __restrict__ out, int n) {
    int node = (blockIdx.x * blockDim.x + threadIdx.x) >> 5;
    int lane = threadIdx.x & 31;
    if (node >= n) return;
    float ax = 0.f, ay = 0.f;
    agg_body(xw, node, lane, ax, ay);
    float ds = g_dis[node];
    float d2 = ds * ds;
    float2 xv = ld_h2(xw, node, lane);
    float2 bb = __ldg((const float2*)b2 + lane);
    float h0 = fmaxf(fmaf(d2, xv.x, ax) + bb.x, 0.f);
    float h1 = fmaxf(fmaf(d2, xv.y, ay) + bb.y, 0.f);
    float2 w = __ldg((const float2*)W3 + lane);
    float sum = fmaf(h0, w.x, h1 * w.y);
#pragma unroll
    for (int off = 16; off; off >>= 1)
        sum += __shfl_xor_sync(0xffffffffu, sum, off);
    if (lane == 0) out[node] = sum + b3[0];
}

extern "C" void kernel_launch(void* const* d_in, const int* in_sizes, int n_in,
                              void* d_out, int out_size) {
    const float* x   = (const float*)d_in[0];
    const int*   ei  = (const int*)d_in[1];       // int32 (JAX x64 disabled)
    const float* ew  = (const float*)d_in[2];
    // d_in[3] = batch (unused)
    const float* W1  = (const float*)d_in[4];
    const float* b1  = (const float*)d_in[5];
    const float* W2  = (const float*)d_in[6];
    const float* b2  = (const float*)d_in[7];
    const float* W3  = (const float*)d_in[8];
    const float* b3  = (const float*)d_in[9];
    float*       out = (float*)d_out;

    const int n = in_sizes[0] / 128;   // 100000
    const int E = in_sizes[1] / 2;     // 1600000
    const int* src = ei;
    const int* dst = ei + E;

    __half *dA, *dB;
    cudaGetSymbolAddress((void**)&dA, g_bufA);
    cudaGetSymbolAddress((void**)&dB, g_bufB);

    const int TB = 256;
    const int NB = (n + SCAN_CHUNK - 1) / SCAN_CHUNK;
    const int GB = (n + 127) / 128;

    // fork: CSR chain on s2, gemm128 on stream 0
    cudaStream_t s2;
    cudaEvent_t evA, evB;
    cudaStreamCreateWithFlags(&s2, cudaStreamNonBlocking);
    cudaEventCreateWithFlags(&evA, cudaEventDisableTiming);
    cudaEventCreateWithFlags(&evB, cudaEventDisableTiming);

    cudaEventRecord(evA, 0);
    cudaStreamWaitEvent(s2, evA, 0);

    // -- CSR chain (s2)
    k_zero_dc<<<(n + TB - 1) / TB, TB, 0, s2>>>(n);
    k_deg_hist<<<(E + TB - 1) / TB, TB, 0, s2>>>(dst, ew, E);
    k_scan1<<<NB, 1024, 0, s2>>>(n);
    k_scan2<<<1, 1024, 0, s2>>>(NB, n, E);
    k_scan3<<<(n + TB - 1) / TB, TB, 0, s2>>>(n);
    k_scatter<<<(E + TB - 1) / TB, TB, 0, s2>>>(src, dst, ew, E);
    cudaEventRecord(evB, s2);

    // -- stream 0: xw1 = x @ W1^T (tensor cores, fp16 out)
    k_gemm_tc<128, false><<<GB, TB>>>(x, W1, dA, n);

    // join, then serial tail
    cudaStreamWaitEvent(0, evB, 0);
    k_agg_relu<<<(n * 32 + TB - 1) / TB, TB>>>(dA, b1, dB, n);
    k_gemm_tc<64, true><<<GB, TB>>>(dB, W2, dA, n);
    k_agg_head<<<(n * 32 + TB - 1) / TB, TB>>>(dA, b2, W3, b3, out, n);
}